// round 3
// baseline (speedup 1.0000x reference)
#include <cuda_runtime.h>
#include <math.h>

// ---------------- static problem config ----------------
#define B_   8
#define Q_   20
#define P_   12
#define N_   4096
#define G_   2048
#define FAC_ 64
#define M_   (Q_ * FAC_)   // 1280
#define KNN_ 7             // k-1 neighbors (self excluded)
#define PAD_COST 1.0e6
#define REP_EPS 1e-12f
#define BW2 0.0009f        // 0.03^2
#define RADIUS_ 0.07f

// ---------------- device scratch (no allocs allowed) ----------------
__device__ float g_cham [B_][Q_][P_];
__device__ float g_nsim [B_][Q_][P_];
__device__ float g_ddiff[B_][Q_][P_];
__device__ float g_cost [B_][Q_][Q_];   // padded square (cols >= P_ get PAD_COST)
__device__ float g_cnt  [B_][P_];
__device__ int   g_rows [B_][P_];
__device__ int   g_mask_mode;           // 0 = uint8 bool, 1 = float32, 2 = int32
// accumulators: 0=cls_sum 1=param_sum 2=pvd_sum 3=rep_sum 4=sum_m_L1 5=sum_m_L2 6=sum_g_L1 7=sum_g_L2
__device__ float g_acc[8];

// ---------------- mask loader (dtype-agnostic) ----------------
__device__ __forceinline__ bool mask_at(const void* m, long idx, int mode) {
    if (mode == 0) return ((const unsigned char*)m)[idx] != 0;
    if (mode == 1) return ((const float*)m)[idx] != 0.f;
    return ((const int*)m)[idx] != 0;
}

// ---------------- kernel 0: zero accumulators + detect mask dtype ----------------
__global__ void k_init(const unsigned char* __restrict__ mraw) {
    if (threadIdx.x < 8) g_acc[threadIdx.x] = 0.f;
    if (threadIdx.x == 0) {
        // Sniff first 8192 bytes. float32 masks contain bytes 0x80/0x3F;
        // uint8 bool masks have value-1 bytes at offsets %4 != 0;
        // int32 masks have 0/1 bytes only, ones exclusively at offsets %4 == 0.
        int mode = 2;
        bool sawBig = false, sawOddOne = false;
        for (int i = 0; i < 8192; i++) {
            unsigned char v = mraw[i];
            if (v > 1) { sawBig = true; break; }
            if (v == 1 && (i & 3) != 0) sawOddOne = true;
        }
        if (sawBig) mode = 1;
        else if (sawOddOne) mode = 0;
        g_mask_mode = mode;
    }
}

// ---------------- kernel 1: cost matrix + mask counts (B*Q blocks) ----------------
__global__ void k_cost(const float* __restrict__ points,
                       const float* __restrict__ pn, const float* __restrict__ pd,
                       const float* __restrict__ gn, const float* __restrict__ gd,
                       const void* __restrict__ mask) {
    int b = blockIdx.x / Q_, q = blockIdx.x % Q_;
    int tid = threadIdx.x;
    int mode = g_mask_mode;
    float nx = pn[(b * Q_ + q) * 3 + 0];
    float ny = pn[(b * Q_ + q) * 3 + 1];
    float nz = pn[(b * Q_ + q) * 3 + 2];
    float dq = pd[b * Q_ + q];

    __shared__ float s_acc[P_];
    __shared__ float s_cnt[P_];
    if (tid < P_) { s_acc[tid] = 0.f; s_cnt[tid] = 0.f; }
    __syncthreads();

    float acc[P_], cnta[P_];
    #pragma unroll
    for (int p = 0; p < P_; p++) { acc[p] = 0.f; cnta[p] = 0.f; }

    const float* pb = points + (size_t)b * N_ * 3;
    const long mbase = (long)b * P_ * N_;
    for (int n = tid; n < N_; n += 256) {
        float px = pb[n * 3 + 0], py = pb[n * 3 + 1], pz = pb[n * 3 + 2];
        float pp = fabsf(px * nx + py * ny + pz * nz - dq);
        #pragma unroll
        for (int p = 0; p < P_; p++) {
            bool m = mask_at(mask, mbase + (long)p * N_ + n, mode);
            acc[p]  += m ? pp : 0.f;
            cnta[p] += m ? 1.f : 0.f;
        }
    }
    #pragma unroll
    for (int p = 0; p < P_; p++) {
        float v = acc[p], c = cnta[p];
        #pragma unroll
        for (int off = 16; off; off >>= 1) {
            v += __shfl_down_sync(0xffffffffu, v, off);
            c += __shfl_down_sync(0xffffffffu, c, off);
        }
        if ((tid & 31) == 0) { atomicAdd(&s_acc[p], v); atomicAdd(&s_cnt[p], c); }
    }
    __syncthreads();

    if (tid < P_) {
        int p = tid;
        float cnt = s_cnt[p];
        float cham = s_acc[p] / fmaxf(cnt, 1.f);
        float ns = 1.f - fabsf(nx * gn[(b * P_ + p) * 3 + 0] +
                               ny * gn[(b * P_ + p) * 3 + 1] +
                               nz * gn[(b * P_ + p) * 3 + 2]);
        float dd = fabsf(dq - gd[b * P_ + p]);
        int has = cnt > 0.f;
        g_cham[b][q][p]  = cham;
        g_nsim[b][q][p]  = ns;
        g_ddiff[b][q][p] = dd;
        g_cost[b][q][p]  = ns + 0.5f * dd + 5.f * (has ? cham : 1.f);
        if (q == 0) g_cnt[b][p] = cnt;
    } else if (tid < Q_) {
        g_cost[b][q][tid] = (float)PAD_COST;
    }
}

// ---------------- kernel 2: Hungarian (JV) — one warp per batch ----------------
__global__ void k_hungarian() {
    const int n = Q_;                // 20
    int b = blockIdx.x;
    int lane = threadIdx.x;
    const unsigned FULL = 0xffffffffu;

    __shared__ double u[Q_ + 1], v[Q_ + 1], minv[Q_ + 1];
    __shared__ int pcol[Q_ + 1], way[Q_ + 1], used[Q_ + 1];

    if (lane <= n) { u[lane] = 0.0; v[lane] = 0.0; pcol[lane] = 0; way[lane] = 0; }
    __syncwarp();

    for (int i = 1; i <= n; i++) {
        if (lane == 0) pcol[0] = i;
        if (lane <= n) { minv[lane] = 1e18; used[lane] = 0; }
        __syncwarp();
        int j0 = 0;
        while (true) {
            if (lane == 0) used[j0] = 1;
            __syncwarp();
            int i0 = pcol[j0];
            double val = 1e18; int jj = lane + 64;  // large index so real candidates win ties
            if (lane >= 1 && lane <= n && !used[lane]) {
                double cur = (double)g_cost[b][i0 - 1][lane - 1] - u[i0] - v[lane];
                if (cur < minv[lane]) { minv[lane] = cur; way[lane] = j0; }
                val = minv[lane]; jj = lane;
            }
            #pragma unroll
            for (int off = 16; off; off >>= 1) {
                double ov = __shfl_down_sync(FULL, val, off);
                int oj    = __shfl_down_sync(FULL, jj, off);
                if (ov < val || (ov == val && oj < jj)) { val = ov; jj = oj; }
            }
            double delta = __shfl_sync(FULL, val, 0);
            int j1       = __shfl_sync(FULL, jj, 0);
            __syncwarp();
            if (lane <= n) {
                if (used[lane]) { u[pcol[lane]] += delta; v[lane] -= delta; }
                else            { minv[lane] -= delta; }
            }
            __syncwarp();
            j0 = j1;
            if (pcol[j0] == 0) break;
        }
        if (lane == 0) {
            while (j0 != 0) { int j1 = way[j0]; pcol[j0] = pcol[j1]; j0 = j1; }
        }
        __syncwarp();
    }
    if (lane >= 1 && lane <= P_) g_rows[b][lane - 1] = pcol[lane] - 1;
}

// ---------------- kernel 3: cls / param / pvd losses (1 block) ----------------
__global__ void k_cls(const float* __restrict__ logits) {
    int t = threadIdx.x;   // 256 threads
    float c_cls = 0.f, c_par = 0.f, c_pvd = 0.f;
    if (t < B_ * Q_) {
        int b = t / Q_, q = t % Q_;
        float tgt = 0.f;
        #pragma unroll
        for (int p = 0; p < P_; p++) tgt += (g_rows[b][p] == q) ? 1.f : 0.f;
        float x = logits[b * Q_ + q];
        c_cls = fmaxf(x, 0.f) - x * tgt + log1pf(expf(-fabsf(x)));
    }
    if (t < B_ * P_) {
        int b = t / P_, p = t % P_;
        int r = g_rows[b][p];
        c_par = g_nsim[b][r][p] + g_ddiff[b][r][p];
        c_pvd = (g_cnt[b][p] > 0.f) ? g_cham[b][r][p] : 0.f;
    }
    __shared__ float s0[256], s1[256], s2[256];
    s0[t] = c_cls; s1[t] = c_par; s2[t] = c_pvd;
    __syncthreads();
    for (int off = 128; off; off >>= 1) {
        if (t < off) { s0[t] += s0[t + off]; s1[t] += s1[t + off]; s2[t] += s2[t + off]; }
        __syncthreads();
    }
    if (t == 0) { g_acc[0] = s0[0]; g_acc[1] = s1[0]; g_acc[2] = s2[0]; }
}

// ---------------- kernel 4: repulsion (B*Q blocks, 64 threads) ----------------
__global__ void k_rep(const float* __restrict__ rec) {
    int b = blockIdx.x / Q_, q = blockIdx.x % Q_;
    int i = threadIdx.x;   // 64
    __shared__ float sx[FAC_], sy[FAC_], sz[FAC_];
    const float* base = rec + (size_t)(b * M_ + q * FAC_) * 3;
    sx[i] = base[i * 3 + 0]; sy[i] = base[i * 3 + 1]; sz[i] = base[i * 3 + 2];
    __syncthreads();
    float px = sx[i], py = sy[i], pz = sz[i];
    float best[KNN_];
    #pragma unroll
    for (int k = 0; k < KNN_; k++) best[k] = 1e30f;
    for (int j = 0; j < FAC_; j++) {
        if (j == i) continue;
        float dx = px - sx[j], dy = py - sy[j], dz = pz - sz[j];
        float d2 = dx * dx + dy * dy + dz * dz;
        float vv = d2;
        #pragma unroll
        for (int k = 0; k < KNN_; k++) {
            float lo = fminf(best[k], vv);
            vv = fmaxf(best[k], vv);
            best[k] = lo;
        }
    }
    float s = 0.f;
    #pragma unroll
    for (int k = 0; k < KNN_; k++) {
        float dn = fmaxf(best[k], REP_EPS);
        s += (RADIUS_ - sqrtf(dn)) * expf(-dn / BW2);
    }
    #pragma unroll
    for (int off = 16; off; off >>= 1) s += __shfl_down_sync(0xffffffffu, s, off);
    __shared__ float sw[2];
    if ((i & 31) == 0) sw[i >> 5] = s;
    __syncthreads();
    if (i == 0) {
        float tot = sw[0] + sw[1];
        float val = fmaxf(tot / (float)(FAC_ * KNN_), 0.f);
        atomicAdd(&g_acc[3], val);
    }
}

// ---------------- kernels 5/6: fine chamfer ----------------
__global__ void k_cham_m(const float* __restrict__ rec, const float* __restrict__ gt) {
    int b = blockIdx.x / (M_ / 256);
    int chunk = blockIdx.x % (M_ / 256);
    int t = threadIdx.x;
    int m = chunk * 256 + t;
    float px = rec[(size_t)(b * M_ + m) * 3 + 0];
    float py = rec[(size_t)(b * M_ + m) * 3 + 1];
    float pz = rec[(size_t)(b * M_ + m) * 3 + 2];
    float m1 = 1e30f, m2 = 1e30f;
    __shared__ float tx[256], ty[256], tz[256];
    const float* gb = gt + (size_t)b * G_ * 3;
    for (int base = 0; base < G_; base += 256) {
        tx[t] = gb[(base + t) * 3 + 0];
        ty[t] = gb[(base + t) * 3 + 1];
        tz[t] = gb[(base + t) * 3 + 2];
        __syncthreads();
        #pragma unroll 4
        for (int j = 0; j < 256; j++) {
            float dx = px - tx[j], dy = py - ty[j], dz = pz - tz[j];
            float ax = fabsf(dx), ay = fabsf(dy), az = fabsf(dz);
            m1 = fminf(m1, ax + ay + az);
            m2 = fminf(m2, dx * dx + dy * dy + dz * dz);
        }
        __syncthreads();
    }
    #pragma unroll
    for (int off = 16; off; off >>= 1) {
        m1 += __shfl_down_sync(0xffffffffu, m1, off);
        m2 += __shfl_down_sync(0xffffffffu, m2, off);
    }
    __shared__ float w1[8], w2[8];
    if ((t & 31) == 0) { w1[t >> 5] = m1; w2[t >> 5] = m2; }
    __syncthreads();
    if (t == 0) {
        float a = 0.f, c = 0.f;
        #pragma unroll
        for (int w = 0; w < 8; w++) { a += w1[w]; c += w2[w]; }
        atomicAdd(&g_acc[4], a);
        atomicAdd(&g_acc[5], c);
    }
}

__global__ void k_cham_g(const float* __restrict__ rec, const float* __restrict__ gt) {
    int b = blockIdx.x / (G_ / 256);
    int chunk = blockIdx.x % (G_ / 256);
    int t = threadIdx.x;
    int g = chunk * 256 + t;
    float px = gt[(size_t)(b * G_ + g) * 3 + 0];
    float py = gt[(size_t)(b * G_ + g) * 3 + 1];
    float pz = gt[(size_t)(b * G_ + g) * 3 + 2];
    float m1 = 1e30f, m2 = 1e30f;
    __shared__ float tx[256], ty[256], tz[256];
    const float* rb = rec + (size_t)b * M_ * 3;
    for (int base = 0; base < M_; base += 256) {
        tx[t] = rb[(base + t) * 3 + 0];
        ty[t] = rb[(base + t) * 3 + 1];
        tz[t] = rb[(base + t) * 3 + 2];
        __syncthreads();
        #pragma unroll 4
        for (int j = 0; j < 256; j++) {
            float dx = px - tx[j], dy = py - ty[j], dz = pz - tz[j];
            float ax = fabsf(dx), ay = fabsf(dy), az = fabsf(dz);
            m1 = fminf(m1, ax + ay + az);
            m2 = fminf(m2, dx * dx + dy * dy + dz * dz);
        }
        __syncthreads();
    }
    #pragma unroll
    for (int off = 16; off; off >>= 1) {
        m1 += __shfl_down_sync(0xffffffffu, m1, off);
        m2 += __shfl_down_sync(0xffffffffu, m2, off);
    }
    __shared__ float w1[8], w2[8];
    if ((t & 31) == 0) { w1[t >> 5] = m1; w2[t >> 5] = m2; }
    __syncthreads();
    if (t == 0) {
        float a = 0.f, c = 0.f;
        #pragma unroll
        for (int w = 0; w < 8; w++) { a += w1[w]; c += w2[w]; }
        atomicAdd(&g_acc[6], a);
        atomicAdd(&g_acc[7], c);
    }
}

// ---------------- kernel 7: final combine ----------------
__global__ void k_final(float* __restrict__ out) {
    float cls   = g_acc[0] / (float)(B_ * Q_);
    float param = g_acc[1] / (float)(B_ * P_);
    float pvd   = g_acc[2] / (float)(B_ * P_);
    float rep   = g_acc[3] / (float)(B_ * Q_);
    float ch1 = 0.5f * (g_acc[4] / (float)(B_ * M_) + g_acc[6] / (float)(B_ * G_));
    float ch2 = 0.5f * (g_acc[5] / (float)(B_ * M_) + g_acc[7] / (float)(B_ * G_));
    out[0] = cls + 0.5f * param + 20.f * pvd + rep + ch1 + ch2;
}

// ---------------- host launcher ----------------
extern "C" void kernel_launch(void* const* d_in, const int* in_sizes, int n_in,
                              void* d_out, int out_size) {
    const float* pred_logits = nullptr;
    const float* pred_normals = nullptr;
    const float* pred_distances = nullptr;
    const float* gt_normals = nullptr;
    const float* gt_distances = nullptr;
    const void*  gt_masks = nullptr;
    const float* points = nullptr;
    const float* rec = nullptr;
    const float* gt = nullptr;
    int seen160 = 0;
    for (int i = 0; i < n_in; i++) {
        switch (in_sizes[i]) {
            case B_ * Q_:            // 160 — logits first, distances second (dict & signature order)
                if (seen160++ == 0) pred_logits = (const float*)d_in[i];
                else pred_distances = (const float*)d_in[i];
                break;
            case B_ * Q_ * 3: pred_normals = (const float*)d_in[i]; break;        // 480
            case B_ * P_ * 3: gt_normals = (const float*)d_in[i]; break;          // 288
            case B_ * P_: gt_distances = (const float*)d_in[i]; break;            // 96
            case B_ * P_ * N_: gt_masks = d_in[i]; break;                         // 393216
            case B_ * N_ * 3: points = (const float*)d_in[i]; break;              // 98304
            case B_ * M_ * 3: rec = (const float*)d_in[i]; break;                 // 30720
            case B_ * G_ * 3: gt = (const float*)d_in[i]; break;                  // 49152
            default: break;                                                        // gt_index unused
        }
    }

    k_init<<<1, 32>>>((const unsigned char*)gt_masks);
    k_cost<<<B_ * Q_, 256>>>(points, pred_normals, pred_distances,
                             gt_normals, gt_distances, gt_masks);
    k_hungarian<<<B_, 32>>>();
    k_cls<<<1, 256>>>(pred_logits);
    k_rep<<<B_ * Q_, FAC_>>>(rec);
    k_cham_m<<<B_ * (M_ / 256), 256>>>(rec, gt);
    k_cham_g<<<B_ * (G_ / 256), 256>>>(rec, gt);
    k_final<<<1, 1>>>((float*)d_out);
}

// round 4
// speedup vs baseline: 6.3003x; 6.3003x over previous
#include <cuda_runtime.h>
#include <math.h>

// ---------------- static problem config ----------------
#define B_   8
#define Q_   20
#define P_   12
#define N_   4096
#define G_   2048
#define FAC_ 64
#define M_   1280
#define KNN_ 7
#define REP_EPS 1e-12f
#define BW2 0.0009f
#define RADIUS_ 0.07f

#define BM (B_*M_)           // 10240
#define BG (B_*G_)           // 16384
#define MINW (2*BM + 2*BG)   // 53248

#define GSPLIT 4
#define MSPLIT 5
#define GM_BLOCKS (B_*(M_/256)*GSPLIT)   // 160
#define GG_BLOCKS (B_*(G_/256)*MSPLIT)   // 320
#define REP_BLOCKS (B_*Q_/4)             // 40
#define GEOM_BLOCKS (GM_BLOCKS + GG_BLOCKS + REP_BLOCKS)

// ---------------- device scratch ----------------
__device__ float g_cham [B_][Q_][P_];
__device__ float g_nsim [B_][Q_][P_];
__device__ float g_ddiff[B_][Q_][P_];
__device__ float g_costT[B_][P_][Q_];   // transposed: rows = gt planes, cols = queries
__device__ float g_cnt  [B_][P_];
__device__ int   g_rows [B_][P_];
__device__ float g_acc[4];              // 0=cls_sum 1=param_sum 2=pvd_sum 3=rep_sum
// min buffers: [0,BM) m-L1, [BM,2BM) m-L2, [2BM,2BM+BG) g-L1, [2BM+BG,..) g-L2
__device__ unsigned int g_minbuf[MINW];

// ---------------- kernel 1: cost matrix + counts + buffer init ----------------
template<int MODE>
__device__ __forceinline__ void accum_masked(const void* __restrict__ mask, long mbase,
    const float* __restrict__ pb, float nx, float ny, float nz, float dq,
    int tid, float* acc, float* cnt)
{
    for (int n = tid; n < N_; n += 256) {
        float px = pb[n*3+0], py = pb[n*3+1], pz = pb[n*3+2];
        float pp = fabsf(px*nx + py*ny + pz*nz - dq);
        #pragma unroll
        for (int p = 0; p < P_; p++) {
            long idx = mbase + (long)p * N_ + n;
            bool m;
            if (MODE == 0)      m = ((const unsigned char*)mask)[idx] != 0;
            else if (MODE == 1) m = ((const float*)mask)[idx] != 0.f;
            else                m = ((const int*)mask)[idx] != 0;
            acc[p] += m ? pp : 0.f;
            cnt[p] += m ? 1.f : 0.f;
        }
    }
}

__global__ void __launch_bounds__(256) k_cost(const float* __restrict__ points,
                       const float* __restrict__ pn, const float* __restrict__ pd,
                       const float* __restrict__ gn, const float* __restrict__ gd,
                       const void* __restrict__ mask)
{
    int b = blockIdx.x / Q_, q = blockIdx.x % Q_;
    int tid = threadIdx.x;

    // init min buffers + accumulators (chip-wide strided; runs before k_geom/k_hung)
    int gtid = blockIdx.x * 256 + tid;
    for (int i = gtid; i < MINW; i += (B_*Q_) * 256) g_minbuf[i] = 0x7F800000u; // +inf bits
    if (gtid < 4) g_acc[gtid] = 0.f;

    // mask dtype detection: block-parallel scan of first 8KB
    const unsigned char* mraw = (const unsigned char*)mask;
    bool big = false, odd = false;
    #pragma unroll 4
    for (int i = tid*32; i < tid*32 + 32; i++) {
        unsigned char v = mraw[i];
        big |= (v > 1);
        odd |= (v == 1) && ((i & 3) != 0);
    }
    int anyBig = __syncthreads_or(big ? 1 : 0);
    int anyOdd = __syncthreads_or(odd ? 1 : 0);
    int mode = anyBig ? 1 : (anyOdd ? 0 : 2);   // 1=float32, 0=uint8, 2=int32

    float nx = pn[(b*Q_ + q)*3 + 0];
    float ny = pn[(b*Q_ + q)*3 + 1];
    float nz = pn[(b*Q_ + q)*3 + 2];
    float dq = pd[b*Q_ + q];

    __shared__ float s_acc[P_], s_cnt[P_];
    if (tid < P_) { s_acc[tid] = 0.f; s_cnt[tid] = 0.f; }
    __syncthreads();

    float acc[P_], cnt[P_];
    #pragma unroll
    for (int p = 0; p < P_; p++) { acc[p] = 0.f; cnt[p] = 0.f; }

    const float* pb = points + (size_t)b * N_ * 3;
    const long mbase = (long)b * P_ * N_;
    if (mode == 1)      accum_masked<1>(mask, mbase, pb, nx, ny, nz, dq, tid, acc, cnt);
    else if (mode == 0) accum_masked<0>(mask, mbase, pb, nx, ny, nz, dq, tid, acc, cnt);
    else                accum_masked<2>(mask, mbase, pb, nx, ny, nz, dq, tid, acc, cnt);

    #pragma unroll
    for (int p = 0; p < P_; p++) {
        float v = acc[p], c = cnt[p];
        #pragma unroll
        for (int off = 16; off; off >>= 1) {
            v += __shfl_down_sync(0xffffffffu, v, off);
            c += __shfl_down_sync(0xffffffffu, c, off);
        }
        if ((tid & 31) == 0) { atomicAdd(&s_acc[p], v); atomicAdd(&s_cnt[p], c); }
    }
    __syncthreads();

    if (tid < P_) {
        int p = tid;
        float c = s_cnt[p];
        float cham = s_acc[p] / fmaxf(c, 1.f);
        float ns = 1.f - fabsf(nx*gn[(b*P_+p)*3+0] + ny*gn[(b*P_+p)*3+1] + nz*gn[(b*P_+p)*3+2]);
        float dd = fabsf(dq - gd[b*P_ + p]);
        int has = c > 0.f;
        g_cham [b][q][p] = cham;
        g_nsim [b][q][p] = ns;
        g_ddiff[b][q][p] = dd;
        g_costT[b][p][q] = ns + 0.5f*dd + 5.f*(has ? cham : 1.f);
        if (q == 0) g_cnt[b][p] = c;
    }
}

// ---------------- kernel 2: geometry (chamfer both dirs + repulsion) ----------------
__global__ void __launch_bounds__(256) k_geom(const float* __restrict__ rec,
                                              const float* __restrict__ gt)
{
    int bid = blockIdx.x;
    int t = threadIdx.x;

    if (bid < GM_BLOCKS) {
        // chamfer dir 1: per reconstructed point, min over a G-slice
        int gs = bid % GSPLIT;
        int mc = (bid / GSPLIT) % (M_/256);
        int b  = bid / (GSPLIT * (M_/256));
        int m = mc*256 + t;
        const float* rp = rec + ((size_t)b*M_ + m)*3;
        float px = rp[0], py = rp[1], pz = rp[2];
        float m1 = 1e30f, m2 = 1e30f;
        __shared__ float tx[256], ty[256], tz[256];
        const float* gb = gt + (size_t)b*G_*3;
        int g0 = gs * (G_/GSPLIT);
        for (int base = g0; base < g0 + G_/GSPLIT; base += 256) {
            tx[t] = gb[(base+t)*3+0]; ty[t] = gb[(base+t)*3+1]; tz[t] = gb[(base+t)*3+2];
            __syncthreads();
            #pragma unroll 8
            for (int j = 0; j < 256; j++) {
                float dx = px-tx[j], dy = py-ty[j], dz = pz-tz[j];
                float l1 = fabsf(dx) + fabsf(dy) + fabsf(dz);
                float l2 = dx*dx + dy*dy + dz*dz;
                m1 = fminf(m1, l1); m2 = fminf(m2, l2);
            }
            __syncthreads();
        }
        atomicMin(&g_minbuf[b*M_ + m],      __float_as_uint(m1));
        atomicMin(&g_minbuf[BM + b*M_ + m], __float_as_uint(m2));
    } else if (bid < GM_BLOCKS + GG_BLOCKS) {
        // chamfer dir 2: per gt point, min over an M-slice (1 tile of 256)
        int id = bid - GM_BLOCKS;
        int ms = id % MSPLIT;
        int gc = (id / MSPLIT) % (G_/256);
        int b  = id / (MSPLIT * (G_/256));
        int g = gc*256 + t;
        const float* gp = gt + ((size_t)b*G_ + g)*3;
        float px = gp[0], py = gp[1], pz = gp[2];
        float m1 = 1e30f, m2 = 1e30f;
        __shared__ float tx[256], ty[256], tz[256];
        const float* rb = rec + (size_t)b*M_*3;
        int base = ms*256;
        tx[t] = rb[(base+t)*3+0]; ty[t] = rb[(base+t)*3+1]; tz[t] = rb[(base+t)*3+2];
        __syncthreads();
        #pragma unroll 8
        for (int j = 0; j < 256; j++) {
            float dx = px-tx[j], dy = py-ty[j], dz = pz-tz[j];
            float l1 = fabsf(dx) + fabsf(dy) + fabsf(dz);
            float l2 = dx*dx + dy*dy + dz*dz;
            m1 = fminf(m1, l1); m2 = fminf(m2, l2);
        }
        atomicMin(&g_minbuf[2*BM + b*G_ + g],      __float_as_uint(m1));
        atomicMin(&g_minbuf[2*BM + BG + b*G_ + g], __float_as_uint(m2));
    } else {
        // repulsion: 4 (b,q) groups per block, 64 threads each
        int id = bid - GM_BLOCKS - GG_BLOCKS;   // 0..39
        int sub = t >> 6;                        // 0..3
        int i = t & 63;
        int gq = id*4 + sub;
        int b = gq / Q_, q = gq % Q_;
        __shared__ float sx[4][FAC_], sy[4][FAC_], sz[4][FAC_];
        const float* base = rec + ((size_t)b*M_ + q*FAC_)*3;
        sx[sub][i] = base[i*3+0]; sy[sub][i] = base[i*3+1]; sz[sub][i] = base[i*3+2];
        __syncthreads();
        float px = sx[sub][i], py = sy[sub][i], pz = sz[sub][i];
        float best[KNN_];
        #pragma unroll
        for (int k = 0; k < KNN_; k++) best[k] = 1e30f;
        for (int j = 0; j < FAC_; j++) {
            if (j == i) continue;
            float dx = px-sx[sub][j], dy = py-sy[sub][j], dz = pz-sz[sub][j];
            float vv = dx*dx + dy*dy + dz*dz;
            #pragma unroll
            for (int k = 0; k < KNN_; k++) {
                float lo = fminf(best[k], vv);
                vv = fmaxf(best[k], vv);
                best[k] = lo;
            }
        }
        float s = 0.f;
        #pragma unroll
        for (int k = 0; k < KNN_; k++) {
            float dn = fmaxf(best[k], REP_EPS);
            s += (RADIUS_ - sqrtf(dn)) * expf(-dn / BW2);
        }
        #pragma unroll
        for (int off = 16; off; off >>= 1) s += __shfl_down_sync(0xffffffffu, s, off);
        __shared__ float sw[8];
        if ((t & 31) == 0) sw[t >> 5] = s;
        __syncthreads();
        if (i == 0) {
            float tot = sw[sub*2] + sw[sub*2 + 1];
            atomicAdd(&g_acc[3], fmaxf(tot / (float)(FAC_*KNN_), 0.f));
        }
    }
}

// ---------------- kernel 3: Hungarian (transposed 12x20 JV, 1 warp/batch) + cls ----------------
__global__ void __launch_bounds__(256) k_hung(const float* __restrict__ logits)
{
    __shared__ double cost_s[B_][P_*Q_];
    __shared__ double u_s[B_][P_ + 1];
    int t = threadIdx.x;
    int w = t >> 5;        // warp = batch
    int lane = t & 31;
    const unsigned FULL = 0xffffffffu;

    const float* csrc = &g_costT[0][0][0];
    for (int idx = lane; idx < P_*Q_; idx += 32)
        cost_s[w][idx] = (double)csrc[w*(P_*Q_) + idx];
    if (lane <= P_) u_s[w][lane] = 0.0;

    double v = 0.0, minv = 0.0;
    int p = 0, way = 0, used = 0;
    __syncwarp();

    for (int i = 1; i <= P_; i++) {
        if (lane == 0) p = i;
        minv = 1e18; used = 0;
        int j0 = 0;
        while (true) {
            if (lane == j0) used = 1;
            int i0 = __shfl_sync(FULL, p, j0);
            double u0 = u_s[w][i0];
            bool active = (lane >= 1) && (lane <= Q_) && !used;
            if (active) {
                double cur = cost_s[w][(i0-1)*Q_ + (lane-1)] - u0 - v;
                if (cur < minv) { minv = cur; way = j0; }
            }
            unsigned long long key;
            if (active) {
                long long s = __double_as_longlong(minv);
                unsigned long long os = (unsigned long long)s ^
                    (0x8000000000000000ULL | (unsigned long long)(s >> 63));
                key = (os & ~63ULL) | (unsigned long long)lane;
            } else key = 0xFFFFFFFFFFFFFFFFULL;
            #pragma unroll
            for (int off = 16; off; off >>= 1) {
                unsigned long long o = __shfl_down_sync(FULL, key, off);
                key = (o < key) ? o : key;
            }
            key = __shfl_sync(FULL, key, 0);
            int j1 = (int)(key & 63ULL);
            double delta = __shfl_sync(FULL, minv, j1);
            if (lane <= Q_) {
                if (used)           { u_s[w][p] += delta; v -= delta; }
                else if (lane >= 1) { minv -= delta; }
            }
            __syncwarp();
            j0 = j1;
            int pj = __shfl_sync(FULL, p, j0);
            if (pj == 0) break;
        }
        // augment along the alternating path
        while (true) {
            int wy = __shfl_sync(FULL, way, j0);
            int pw = __shfl_sync(FULL, p, wy);
            if (lane == j0) p = pw;
            j0 = wy;
            if (j0 == 0) break;
        }
    }
    if (lane >= 1 && lane <= Q_ && p >= 1)
        g_rows[w][p - 1] = lane - 1;   // gt plane (p-1) matched to query (lane-1)
    __syncthreads();

    // ---- cls / param / pvd (256 threads) ----
    float c_cls = 0.f, c_par = 0.f, c_pvd = 0.f;
    if (t < B_*Q_) {
        int b = t / Q_, q = t % Q_;
        float tgt = 0.f;
        #pragma unroll
        for (int pp = 0; pp < P_; pp++) tgt += (g_rows[b][pp] == q) ? 1.f : 0.f;
        float x = logits[t];
        c_cls = fmaxf(x, 0.f) - x*tgt + log1pf(expf(-fabsf(x)));
    }
    if (t < B_*P_) {
        int b = t / P_, pp = t % P_;
        int r = g_rows[b][pp];
        c_par = g_nsim[b][r][pp] + g_ddiff[b][r][pp];
        c_pvd = (g_cnt[b][pp] > 0.f) ? g_cham[b][r][pp] : 0.f;
    }
    __shared__ float s0[256], s1[256], s2[256];
    s0[t] = c_cls; s1[t] = c_par; s2[t] = c_pvd;
    __syncthreads();
    for (int off = 128; off; off >>= 1) {
        if (t < off) { s0[t] += s0[t+off]; s1[t] += s1[t+off]; s2[t] += s2[t+off]; }
        __syncthreads();
    }
    if (t == 0) { g_acc[0] = s0[0]; g_acc[1] = s1[0]; g_acc[2] = s2[0]; }
}

// ---------------- kernel 4: final combine ----------------
__global__ void __launch_bounds__(256) k_final(float* __restrict__ out)
{
    int t = threadIdx.x;
    float s0 = 0.f, s1 = 0.f, s2 = 0.f, s3 = 0.f;
    for (int i = t; i < BM; i += 256) {
        s0 += __uint_as_float(g_minbuf[i]);
        s1 += __uint_as_float(g_minbuf[BM + i]);
    }
    for (int i = t; i < BG; i += 256) {
        s2 += __uint_as_float(g_minbuf[2*BM + i]);
        s3 += __uint_as_float(g_minbuf[2*BM + BG + i]);
    }
    __shared__ float a0[256], a1[256], a2[256], a3[256];
    a0[t] = s0; a1[t] = s1; a2[t] = s2; a3[t] = s3;
    __syncthreads();
    for (int off = 128; off; off >>= 1) {
        if (t < off) { a0[t] += a0[t+off]; a1[t] += a1[t+off]; a2[t] += a2[t+off]; a3[t] += a3[t+off]; }
        __syncthreads();
    }
    if (t == 0) {
        float ch1 = 0.5f * (a0[0] / (float)BM + a2[0] / (float)BG);
        float ch2 = 0.5f * (a1[0] / (float)BM + a3[0] / (float)BG);
        out[0] = g_acc[0] / (float)(B_*Q_)
               + 0.5f  * g_acc[1] / (float)(B_*P_)
               + 20.f  * g_acc[2] / (float)(B_*P_)
               + g_acc[3] / (float)(B_*Q_)
               + ch1 + ch2;
    }
}

// ---------------- host launcher ----------------
extern "C" void kernel_launch(void* const* d_in, const int* in_sizes, int n_in,
                              void* d_out, int out_size) {
    const float* pred_logits = nullptr;
    const float* pred_normals = nullptr;
    const float* pred_distances = nullptr;
    const float* gt_normals = nullptr;
    const float* gt_distances = nullptr;
    const void*  gt_masks = nullptr;
    const float* points = nullptr;
    const float* rec = nullptr;
    const float* gt = nullptr;
    int seen160 = 0;
    for (int i = 0; i < n_in; i++) {
        switch (in_sizes[i]) {
            case B_ * Q_:
                if (seen160++ == 0) pred_logits = (const float*)d_in[i];
                else pred_distances = (const float*)d_in[i];
                break;
            case B_ * Q_ * 3: pred_normals = (const float*)d_in[i]; break;
            case B_ * P_ * 3: gt_normals = (const float*)d_in[i]; break;
            case B_ * P_: gt_distances = (const float*)d_in[i]; break;
            case B_ * P_ * N_: gt_masks = d_in[i]; break;
            case B_ * N_ * 3: points = (const float*)d_in[i]; break;
            case B_ * M_ * 3: rec = (const float*)d_in[i]; break;
            case B_ * G_ * 3: gt = (const float*)d_in[i]; break;
            default: break;  // gt_index unused
        }
    }

    k_cost<<<B_ * Q_, 256>>>(points, pred_normals, pred_distances,
                             gt_normals, gt_distances, gt_masks);
    k_geom<<<GEOM_BLOCKS, 256>>>(rec, gt);
    k_hung<<<1, 256>>>(pred_logits);
    k_final<<<1, 256>>>((float*)d_out);
}

// round 5
// speedup vs baseline: 6.9577x; 1.1044x over previous
#include <cuda_runtime.h>
#include <math.h>

// ---------------- static problem config ----------------
#define B_   8
#define Q_   20
#define P_   12
#define N_   4096
#define G_   2048
#define FAC_ 64
#define M_   1280
#define KNN_ 7
#define REP_EPS 1e-12f
#define BW2 0.0009f
#define RADIUS_ 0.07f

#define BM (B_*M_)           // 10240
#define BG (B_*G_)           // 16384
#define MINW (2*BM + 2*BG)   // 53248

#define COST_BLOCKS (B_*Q_)              // 160
#define GSPLIT 4
#define MSPLIT 5
#define GM_BLOCKS (B_*(M_/256)*GSPLIT)   // 160
#define GG_BLOCKS (B_*(G_/256)*MSPLIT)   // 320
#define REP_BLOCKS (B_*Q_/4)             // 40
#define K1_BLOCKS (COST_BLOCKS + GM_BLOCKS + GG_BLOCKS + REP_BLOCKS)  // 680

// ---------------- device scratch (zero-init is the identity for everything) ----------------
__device__ float g_cham [B_][Q_][P_];
__device__ float g_nsim [B_][Q_][P_];
__device__ float g_ddiff[B_][Q_][P_];
__device__ float g_costT[B_][P_][Q_];   // transposed: rows = gt planes, cols = queries
__device__ float g_cnt  [B_][P_];
__device__ int   g_rows [B_][P_];
__device__ float g_rep_acc;             // repulsion sum (zeroed by k2 after use)
// min buffers hold ~bits(value): max(~bits) == min(value); identity = 0 (static init ok).
// layout: [0,BM) m-L1, [BM,2BM) m-L2, [2BM,2BM+BG) g-L1, [2BM+BG,..) g-L2
__device__ unsigned int g_minbuf[MINW];

// ---------------- masked accumulation helper ----------------
template<int MODE>
__device__ __forceinline__ void accum_masked(const void* __restrict__ mask, long mbase,
    const float* __restrict__ pb, float nx, float ny, float nz, float dq,
    int tid, float* acc, float* cnt)
{
    for (int n = tid; n < N_; n += 256) {
        float px = pb[n*3+0], py = pb[n*3+1], pz = pb[n*3+2];
        float pp = fabsf(px*nx + py*ny + pz*nz - dq);
        #pragma unroll
        for (int p = 0; p < P_; p++) {
            long idx = mbase + (long)p * N_ + n;
            bool m;
            if (MODE == 0)      m = ((const unsigned char*)mask)[idx] != 0;
            else if (MODE == 1) m = ((const float*)mask)[idx] != 0.f;
            else                m = ((const int*)mask)[idx] != 0;
            acc[p] += m ? pp : 0.f;
            cnt[p] += m ? 1.f : 0.f;
        }
    }
}

// ---------------- kernel 1: cost matrix + chamfer + repulsion (fused grid) ----------------
__global__ void __launch_bounds__(256) k1(const float* __restrict__ points,
                       const float* __restrict__ pn, const float* __restrict__ pd,
                       const float* __restrict__ gn, const float* __restrict__ gd,
                       const void* __restrict__ mask,
                       const float* __restrict__ rec, const float* __restrict__ gt)
{
    int bid = blockIdx.x;
    int t = threadIdx.x;

    if (bid < COST_BLOCKS) {
        // ------- cost matrix (b, q) -------
        int b = bid / Q_, q = bid % Q_;

        // mask dtype detection: block-parallel scan of first 8KB
        const unsigned char* mraw = (const unsigned char*)mask;
        bool big = false, odd = false;
        #pragma unroll 4
        for (int i = t*32; i < t*32 + 32; i++) {
            unsigned char v = mraw[i];
            big |= (v > 1);
            odd |= (v == 1) && ((i & 3) != 0);
        }
        int anyBig = __syncthreads_or(big ? 1 : 0);
        int anyOdd = __syncthreads_or(odd ? 1 : 0);
        int mode = anyBig ? 1 : (anyOdd ? 0 : 2);   // 1=float32, 0=uint8, 2=int32

        float nx = pn[(b*Q_ + q)*3 + 0];
        float ny = pn[(b*Q_ + q)*3 + 1];
        float nz = pn[(b*Q_ + q)*3 + 2];
        float dq = pd[b*Q_ + q];

        __shared__ float s_acc[P_], s_cnt[P_];
        if (t < P_) { s_acc[t] = 0.f; s_cnt[t] = 0.f; }
        __syncthreads();

        float acc[P_], cnt[P_];
        #pragma unroll
        for (int p = 0; p < P_; p++) { acc[p] = 0.f; cnt[p] = 0.f; }

        const float* pb = points + (size_t)b * N_ * 3;
        const long mbase = (long)b * P_ * N_;
        if (mode == 1)      accum_masked<1>(mask, mbase, pb, nx, ny, nz, dq, t, acc, cnt);
        else if (mode == 0) accum_masked<0>(mask, mbase, pb, nx, ny, nz, dq, t, acc, cnt);
        else                accum_masked<2>(mask, mbase, pb, nx, ny, nz, dq, t, acc, cnt);

        #pragma unroll
        for (int p = 0; p < P_; p++) {
            float v = acc[p], c = cnt[p];
            #pragma unroll
            for (int off = 16; off; off >>= 1) {
                v += __shfl_down_sync(0xffffffffu, v, off);
                c += __shfl_down_sync(0xffffffffu, c, off);
            }
            if ((t & 31) == 0) { atomicAdd(&s_acc[p], v); atomicAdd(&s_cnt[p], c); }
        }
        __syncthreads();

        if (t < P_) {
            int p = t;
            float c = s_cnt[p];
            float cham = s_acc[p] / fmaxf(c, 1.f);
            float ns = 1.f - fabsf(nx*gn[(b*P_+p)*3+0] + ny*gn[(b*P_+p)*3+1] + nz*gn[(b*P_+p)*3+2]);
            float dd = fabsf(dq - gd[b*P_ + p]);
            int has = c > 0.f;
            g_cham [b][q][p] = cham;
            g_nsim [b][q][p] = ns;
            g_ddiff[b][q][p] = dd;
            g_costT[b][p][q] = ns + 0.5f*dd + 5.f*(has ? cham : 1.f);
            if (q == 0) g_cnt[b][p] = c;
        }
    } else if (bid < COST_BLOCKS + GM_BLOCKS) {
        // ------- chamfer dir 1: per reconstructed point, min over a G-slice -------
        int id = bid - COST_BLOCKS;
        int gs = id % GSPLIT;
        int mc = (id / GSPLIT) % (M_/256);
        int b  = id / (GSPLIT * (M_/256));
        int m = mc*256 + t;
        const float* rp = rec + ((size_t)b*M_ + m)*3;
        float px = rp[0], py = rp[1], pz = rp[2];
        float m1 = 1e30f, m2 = 1e30f;
        __shared__ float tx[256], ty[256], tz[256];
        const float* gb = gt + (size_t)b*G_*3;
        int g0 = gs * (G_/GSPLIT);
        for (int base = g0; base < g0 + G_/GSPLIT; base += 256) {
            tx[t] = gb[(base+t)*3+0]; ty[t] = gb[(base+t)*3+1]; tz[t] = gb[(base+t)*3+2];
            __syncthreads();
            #pragma unroll 8
            for (int j = 0; j < 256; j++) {
                float dx = px-tx[j], dy = py-ty[j], dz = pz-tz[j];
                float l1 = fabsf(dx) + fabsf(dy) + fabsf(dz);
                float l2 = dx*dx + dy*dy + dz*dz;
                m1 = fminf(m1, l1); m2 = fminf(m2, l2);
            }
            __syncthreads();
        }
        atomicMax(&g_minbuf[b*M_ + m],      ~__float_as_uint(m1));
        atomicMax(&g_minbuf[BM + b*M_ + m], ~__float_as_uint(m2));
    } else if (bid < COST_BLOCKS + GM_BLOCKS + GG_BLOCKS) {
        // ------- chamfer dir 2: per gt point, min over an M-slice -------
        int id = bid - COST_BLOCKS - GM_BLOCKS;
        int ms = id % MSPLIT;
        int gc = (id / MSPLIT) % (G_/256);
        int b  = id / (MSPLIT * (G_/256));
        int g = gc*256 + t;
        const float* gp = gt + ((size_t)b*G_ + g)*3;
        float px = gp[0], py = gp[1], pz = gp[2];
        float m1 = 1e30f, m2 = 1e30f;
        __shared__ float tx[256], ty[256], tz[256];
        const float* rb = rec + (size_t)b*M_*3;
        int base = ms*256;
        tx[t] = rb[(base+t)*3+0]; ty[t] = rb[(base+t)*3+1]; tz[t] = rb[(base+t)*3+2];
        __syncthreads();
        #pragma unroll 8
        for (int j = 0; j < 256; j++) {
            float dx = px-tx[j], dy = py-ty[j], dz = pz-tz[j];
            float l1 = fabsf(dx) + fabsf(dy) + fabsf(dz);
            float l2 = dx*dx + dy*dy + dz*dz;
            m1 = fminf(m1, l1); m2 = fminf(m2, l2);
        }
        atomicMax(&g_minbuf[2*BM + b*G_ + g],      ~__float_as_uint(m1));
        atomicMax(&g_minbuf[2*BM + BG + b*G_ + g], ~__float_as_uint(m2));
    } else {
        // ------- repulsion: 4 (b,q) groups per block, 64 threads each -------
        int id = bid - COST_BLOCKS - GM_BLOCKS - GG_BLOCKS;   // 0..39
        int sub = t >> 6;
        int i = t & 63;
        int gq = id*4 + sub;
        int b = gq / Q_, q = gq % Q_;
        __shared__ float sx[4][FAC_], sy[4][FAC_], sz[4][FAC_];
        const float* base = rec + ((size_t)b*M_ + q*FAC_)*3;
        sx[sub][i] = base[i*3+0]; sy[sub][i] = base[i*3+1]; sz[sub][i] = base[i*3+2];
        __syncthreads();
        float px = sx[sub][i], py = sy[sub][i], pz = sz[sub][i];
        float best[KNN_];
        #pragma unroll
        for (int k = 0; k < KNN_; k++) best[k] = 1e30f;
        for (int j = 0; j < FAC_; j++) {
            if (j == i) continue;
            float dx = px-sx[sub][j], dy = py-sy[sub][j], dz = pz-sz[sub][j];
            float vv = dx*dx + dy*dy + dz*dz;
            #pragma unroll
            for (int k = 0; k < KNN_; k++) {
                float lo = fminf(best[k], vv);
                vv = fmaxf(best[k], vv);
                best[k] = lo;
            }
        }
        float s = 0.f;
        #pragma unroll
        for (int k = 0; k < KNN_; k++) {
            float dn = fmaxf(best[k], REP_EPS);
            s += (RADIUS_ - sqrtf(dn)) * expf(-dn / BW2);
        }
        #pragma unroll
        for (int off = 16; off; off >>= 1) s += __shfl_down_sync(0xffffffffu, s, off);
        __shared__ float sw[8];
        if ((t & 31) == 0) sw[t >> 5] = s;
        __syncthreads();
        if (i == 0) {
            float tot = sw[sub*2] + sw[sub*2 + 1];
            atomicAdd(&g_rep_acc, fmaxf(tot / (float)(FAC_*KNN_), 0.f));
        }
    }
}

// ---------------- kernel 2: Hungarian + cls + reductions + final + state restore ----------------
__global__ void __launch_bounds__(256) k2(const float* __restrict__ logits,
                                          float* __restrict__ out)
{
    __shared__ double cost_s[B_][P_*Q_];
    __shared__ double u_s[B_][P_ + 1];
    __shared__ float red[4][256];
    int t = threadIdx.x;
    int w = t >> 5;        // warp = batch
    int lane = t & 31;
    const unsigned FULL = 0xffffffffu;

    const float* csrc = &g_costT[0][0][0];
    for (int idx = lane; idx < P_*Q_; idx += 32)
        cost_s[w][idx] = (double)csrc[w*(P_*Q_) + idx];
    if (lane <= P_) u_s[w][lane] = 0.0;

    double v = 0.0, minv = 0.0;
    int p = 0, way = 0, used = 0;
    __syncwarp();

    for (int i = 1; i <= P_; i++) {
        if (lane == 0) p = i;
        minv = 1e18; used = 0;
        int j0 = 0;
        while (true) {
            if (lane == j0) used = 1;
            int i0 = __shfl_sync(FULL, p, j0);
            double u0 = u_s[w][i0];
            bool active = (lane >= 1) && (lane <= Q_) && !used;
            if (active) {
                double cur = cost_s[w][(i0-1)*Q_ + (lane-1)] - u0 - v;
                if (cur < minv) { minv = cur; way = j0; }
            }
            unsigned long long key;
            if (active) {
                long long s = __double_as_longlong(minv);
                unsigned long long os = (unsigned long long)s ^
                    (0x8000000000000000ULL | (unsigned long long)(s >> 63));
                key = (os & ~63ULL) | (unsigned long long)lane;
            } else key = 0xFFFFFFFFFFFFFFFFULL;
            #pragma unroll
            for (int off = 16; off; off >>= 1) {
                unsigned long long o = __shfl_down_sync(FULL, key, off);
                key = (o < key) ? o : key;
            }
            key = __shfl_sync(FULL, key, 0);
            int j1 = (int)(key & 63ULL);
            double delta = __shfl_sync(FULL, minv, j1);
            if (lane <= Q_) {
                if (used)           { u_s[w][p] += delta; v -= delta; }
                else if (lane >= 1) { minv -= delta; }
            }
            __syncwarp();
            j0 = j1;
            int pj = __shfl_sync(FULL, p, j0);
            if (pj == 0) break;
        }
        while (true) {
            int wy = __shfl_sync(FULL, way, j0);
            int pw = __shfl_sync(FULL, p, wy);
            if (lane == j0) p = pw;
            j0 = wy;
            if (j0 == 0) break;
        }
    }
    if (lane >= 1 && lane <= Q_ && p >= 1)
        g_rows[w][p - 1] = lane - 1;   // gt plane (p-1) matched to query (lane-1)
    __syncthreads();

    // ---- cls / param / pvd ----
    float c_cls = 0.f, c_par = 0.f, c_pvd = 0.f;
    if (t < B_*Q_) {
        int b = t / Q_, q = t % Q_;
        float tgt = 0.f;
        #pragma unroll
        for (int pp = 0; pp < P_; pp++) tgt += (g_rows[b][pp] == q) ? 1.f : 0.f;
        float x = logits[t];
        c_cls = fmaxf(x, 0.f) - x*tgt + log1pf(expf(-fabsf(x)));
    }
    if (t < B_*P_) {
        int b = t / P_, pp = t % P_;
        int r = g_rows[b][pp];
        c_par = g_nsim[b][r][pp] + g_ddiff[b][r][pp];
        c_pvd = (g_cnt[b][pp] > 0.f) ? g_cham[b][r][pp] : 0.f;
    }
    red[0][t] = c_cls; red[1][t] = c_par; red[2][t] = c_pvd; red[3][t] = 0.f;
    __syncthreads();
    for (int off = 128; off; off >>= 1) {
        if (t < off) {
            red[0][t] += red[0][t+off]; red[1][t] += red[1][t+off]; red[2][t] += red[2][t+off];
        }
        __syncthreads();
    }
    __shared__ float cls_s, par_s, pvd_s;
    if (t == 0) { cls_s = red[0][0]; par_s = red[1][0]; pvd_s = red[2][0]; }
    __syncthreads();

    // ---- chamfer min-buffer sums (decode ~bits) + restore zeros ----
    float s0 = 0.f, s1 = 0.f, s2 = 0.f, s3 = 0.f;
    for (int i = t; i < BM; i += 256) {
        s0 += __uint_as_float(~g_minbuf[i]);
        s1 += __uint_as_float(~g_minbuf[BM + i]);
        g_minbuf[i] = 0u; g_minbuf[BM + i] = 0u;
    }
    for (int i = t; i < BG; i += 256) {
        s2 += __uint_as_float(~g_minbuf[2*BM + i]);
        s3 += __uint_as_float(~g_minbuf[2*BM + BG + i]);
        g_minbuf[2*BM + i] = 0u; g_minbuf[2*BM + BG + i] = 0u;
    }
    red[0][t] = s0; red[1][t] = s1; red[2][t] = s2; red[3][t] = s3;
    __syncthreads();
    for (int off = 128; off; off >>= 1) {
        if (t < off) {
            red[0][t] += red[0][t+off]; red[1][t] += red[1][t+off];
            red[2][t] += red[2][t+off]; red[3][t] += red[3][t+off];
        }
        __syncthreads();
    }
    if (t == 0) {
        float ch1 = 0.5f * (red[0][0] / (float)BM + red[2][0] / (float)BG);
        float ch2 = 0.5f * (red[1][0] / (float)BM + red[3][0] / (float)BG);
        float rep = g_rep_acc;
        out[0] = cls_s / (float)(B_*Q_)
               + 0.5f  * par_s / (float)(B_*P_)
               + 20.f  * pvd_s / (float)(B_*P_)
               + rep / (float)(B_*Q_)
               + ch1 + ch2;
        g_rep_acc = 0.f;   // restore for next graph replay
    }
}

// ---------------- host launcher ----------------
extern "C" void kernel_launch(void* const* d_in, const int* in_sizes, int n_in,
                              void* d_out, int out_size) {
    const float* pred_logits = nullptr;
    const float* pred_normals = nullptr;
    const float* pred_distances = nullptr;
    const float* gt_normals = nullptr;
    const float* gt_distances = nullptr;
    const void*  gt_masks = nullptr;
    const float* points = nullptr;
    const float* rec = nullptr;
    const float* gt = nullptr;
    int seen160 = 0;
    for (int i = 0; i < n_in; i++) {
        switch (in_sizes[i]) {
            case B_ * Q_:
                if (seen160++ == 0) pred_logits = (const float*)d_in[i];
                else pred_distances = (const float*)d_in[i];
                break;
            case B_ * Q_ * 3: pred_normals = (const float*)d_in[i]; break;
            case B_ * P_ * 3: gt_normals = (const float*)d_in[i]; break;
            case B_ * P_: gt_distances = (const float*)d_in[i]; break;
            case B_ * P_ * N_: gt_masks = d_in[i]; break;
            case B_ * N_ * 3: points = (const float*)d_in[i]; break;
            case B_ * M_ * 3: rec = (const float*)d_in[i]; break;
            case B_ * G_ * 3: gt = (const float*)d_in[i]; break;
            default: break;  // gt_index unused
        }
    }

    k1<<<K1_BLOCKS, 256>>>(points, pred_normals, pred_distances,
                           gt_normals, gt_distances, gt_masks, rec, gt);
    k2<<<1, 256>>>(pred_logits, (float*)d_out);
}

// round 6
// speedup vs baseline: 11.8727x; 1.7064x over previous
#include <cuda_runtime.h>
#include <math.h>

// ---------------- static problem config ----------------
#define B_   8
#define Q_   20
#define P_   12
#define N_   4096
#define G_   2048
#define FAC_ 64
#define M_   1280
#define KNN_ 7
#define REP_EPS 1e-12f
#define BW2 0.0009f
#define RADIUS_ 0.07f

#define BM (B_*M_)           // 10240
#define BG (B_*G_)           // 16384

#define COST_BLOCKS (B_*Q_)              // 160
#define CH1_BLOCKS (B_*(M_/64))          // 160  (64 rec points per block)
#define CH2_BLOCKS (B_*(G_/64))          // 256  (64 gt points per block)
#define REP_BLOCKS (B_*Q_/4)             // 40
#define K1_BLOCKS (COST_BLOCKS + CH1_BLOCKS + CH2_BLOCKS + REP_BLOCKS)  // 616

// ---------------- device scratch (zero is identity; k2 restores zeros) ----------------
__device__ float g_cham [B_][Q_][P_];
__device__ float g_nsim [B_][Q_][P_];
__device__ float g_ddiff[B_][Q_][P_];
__device__ float g_costT[B_][P_][Q_];   // rows = gt planes, cols = queries
__device__ float g_cnt  [B_][P_];
__device__ int   g_rows [B_][P_];
__device__ float g_accs[8];             // 0=rep 1=mL1 2=mL2 3=gL1 4=gL2

// ---------------- masked accumulation helper ----------------
template<int MODE>
__device__ __forceinline__ void accum_masked(const void* __restrict__ mask, long mbase,
    const float* __restrict__ pb, float nx, float ny, float nz, float dq,
    int tid, float* acc, float* cnt)
{
    for (int n = tid; n < N_; n += 256) {
        float px = pb[n*3+0], py = pb[n*3+1], pz = pb[n*3+2];
        float pp = fabsf(px*nx + py*ny + pz*nz - dq);
        #pragma unroll
        for (int p = 0; p < P_; p++) {
            long idx = mbase + (long)p * N_ + n;
            bool m;
            if (MODE == 0)      m = ((const unsigned char*)mask)[idx] != 0;
            else if (MODE == 1) m = ((const float*)mask)[idx] != 0.f;
            else                m = ((const int*)mask)[idx] != 0;
            acc[p] += m ? pp : 0.f;
            cnt[p] += m ? 1.f : 0.f;
        }
    }
}

// ---------------- chamfer block helper: 64 src points, 4-way target slicing ----------------
// Each block owns 64 source points; thread t handles point (t&63), target slice (t>>6).
// After full scan each point's min is combined across the 4 slices and block-summed.
__device__ __forceinline__ void chamfer_block(
    const float* __restrict__ srcBase,   // 64 consecutive src points (xyz)
    const float* __restrict__ tgtBase,   // tgt cloud (xyz)
    int nTgt, int accL1, int accL2)
{
    int t = threadIdx.x;
    int pi = t & 63, s = t >> 6;
    float px = srcBase[pi*3+0], py = srcBase[pi*3+1], pz = srcBase[pi*3+2];
    float m1 = 1e30f, m2 = 1e30f;
    __shared__ float tx[256], ty[256], tz[256];
    for (int base = 0; base < nTgt; base += 256) {
        tx[t] = tgtBase[(base+t)*3+0];
        ty[t] = tgtBase[(base+t)*3+1];
        tz[t] = tgtBase[(base+t)*3+2];
        __syncthreads();
        int j0 = s * 64;
        #pragma unroll 8
        for (int j = j0; j < j0 + 64; j++) {
            float dx = px-tx[j], dy = py-ty[j], dz = pz-tz[j];
            float l1 = fabsf(dx) + fabsf(dy) + fabsf(dz);
            float l2 = fmaf(dx, dx, fmaf(dy, dy, dz*dz));
            m1 = fminf(m1, l1); m2 = fminf(m2, l2);
        }
        __syncthreads();
    }
    __shared__ float r1[256], r2[256];
    r1[t] = m1; r2[t] = m2;
    __syncthreads();
    if (t < 64) {
        float a1 = fminf(fminf(r1[t], r1[t+64]), fminf(r1[t+128], r1[t+192]));
        float a2 = fminf(fminf(r2[t], r2[t+64]), fminf(r2[t+128], r2[t+192]));
        // warp-sum the 64 per-point mins (2 warps)
        #pragma unroll
        for (int off = 16; off; off >>= 1) {
            a1 += __shfl_down_sync(0xffffffffu, a1, off);
            a2 += __shfl_down_sync(0xffffffffu, a2, off);
        }
        if ((t & 31) == 0) { r1[t] = a1; r2[t] = a2; }
    }
    __syncthreads();
    if (t == 0) {
        atomicAdd(&g_accs[accL1], r1[0] + r1[32]);
        atomicAdd(&g_accs[accL2], r2[0] + r2[32]);
    }
}

// ---------------- kernel 1: cost matrix + chamfer + repulsion (fused grid) ----------------
__global__ void __launch_bounds__(256) k1(const float* __restrict__ points,
                       const float* __restrict__ pn, const float* __restrict__ pd,
                       const float* __restrict__ gn, const float* __restrict__ gd,
                       const void* __restrict__ mask,
                       const float* __restrict__ rec, const float* __restrict__ gt)
{
    int bid = blockIdx.x;
    int t = threadIdx.x;

    if (bid < COST_BLOCKS) {
        // ------- cost matrix (b, q) -------
        int b = bid / Q_, q = bid % Q_;

        // mask dtype detection: block-parallel scan of first 8KB
        const unsigned char* mraw = (const unsigned char*)mask;
        bool big = false, odd = false;
        #pragma unroll 4
        for (int i = t*32; i < t*32 + 32; i++) {
            unsigned char v = mraw[i];
            big |= (v > 1);
            odd |= (v == 1) && ((i & 3) != 0);
        }
        int anyBig = __syncthreads_or(big ? 1 : 0);
        int anyOdd = __syncthreads_or(odd ? 1 : 0);
        int mode = anyBig ? 1 : (anyOdd ? 0 : 2);   // 1=float32, 0=uint8, 2=int32

        float nx = pn[(b*Q_ + q)*3 + 0];
        float ny = pn[(b*Q_ + q)*3 + 1];
        float nz = pn[(b*Q_ + q)*3 + 2];
        float dq = pd[b*Q_ + q];

        __shared__ float s_acc[P_], s_cnt[P_];
        if (t < P_) { s_acc[t] = 0.f; s_cnt[t] = 0.f; }
        __syncthreads();

        float acc[P_], cnt[P_];
        #pragma unroll
        for (int p = 0; p < P_; p++) { acc[p] = 0.f; cnt[p] = 0.f; }

        const float* pb = points + (size_t)b * N_ * 3;
        const long mbase = (long)b * P_ * N_;
        if (mode == 1)      accum_masked<1>(mask, mbase, pb, nx, ny, nz, dq, t, acc, cnt);
        else if (mode == 0) accum_masked<0>(mask, mbase, pb, nx, ny, nz, dq, t, acc, cnt);
        else                accum_masked<2>(mask, mbase, pb, nx, ny, nz, dq, t, acc, cnt);

        #pragma unroll
        for (int p = 0; p < P_; p++) {
            float v = acc[p], c = cnt[p];
            #pragma unroll
            for (int off = 16; off; off >>= 1) {
                v += __shfl_down_sync(0xffffffffu, v, off);
                c += __shfl_down_sync(0xffffffffu, c, off);
            }
            if ((t & 31) == 0) { atomicAdd(&s_acc[p], v); atomicAdd(&s_cnt[p], c); }
        }
        __syncthreads();

        if (t < P_) {
            int p = t;
            float c = s_cnt[p];
            float cham = s_acc[p] / fmaxf(c, 1.f);
            float ns = 1.f - fabsf(nx*gn[(b*P_+p)*3+0] + ny*gn[(b*P_+p)*3+1] + nz*gn[(b*P_+p)*3+2]);
            float dd = fabsf(dq - gd[b*P_ + p]);
            int has = c > 0.f;
            g_cham [b][q][p] = cham;
            g_nsim [b][q][p] = ns;
            g_ddiff[b][q][p] = dd;
            g_costT[b][p][q] = ns + 0.5f*dd + 5.f*(has ? cham : 1.f);
            if (q == 0) g_cnt[b][p] = c;
        }
    } else if (bid < COST_BLOCKS + CH1_BLOCKS) {
        // ------- chamfer dir 1: 64 rec points vs full G -------
        int id = bid - COST_BLOCKS;
        int b  = id / (M_/64);
        int mc = id % (M_/64);
        chamfer_block(rec + ((size_t)b*M_ + mc*64)*3, gt + (size_t)b*G_*3, G_, 1, 2);
    } else if (bid < COST_BLOCKS + CH1_BLOCKS + CH2_BLOCKS) {
        // ------- chamfer dir 2: 64 gt points vs full M -------
        int id = bid - COST_BLOCKS - CH1_BLOCKS;
        int b  = id / (G_/64);
        int gc = id % (G_/64);
        chamfer_block(gt + ((size_t)b*G_ + gc*64)*3, rec + (size_t)b*M_*3, M_, 3, 4);
    } else {
        // ------- repulsion: 4 (b,q) groups per block, 64 threads each -------
        int id = bid - COST_BLOCKS - CH1_BLOCKS - CH2_BLOCKS;   // 0..39
        int sub = t >> 6;
        int i = t & 63;
        int gq = id*4 + sub;
        int b = gq / Q_, q = gq % Q_;
        __shared__ float sx[4][FAC_], sy[4][FAC_], sz[4][FAC_];
        const float* base = rec + ((size_t)b*M_ + q*FAC_)*3;
        sx[sub][i] = base[i*3+0]; sy[sub][i] = base[i*3+1]; sz[sub][i] = base[i*3+2];
        __syncthreads();
        float px = sx[sub][i], py = sy[sub][i], pz = sz[sub][i];
        float best[KNN_];
        #pragma unroll
        for (int k = 0; k < KNN_; k++) best[k] = 1e30f;
        for (int j = 0; j < FAC_; j++) {
            if (j == i) continue;
            float dx = px-sx[sub][j], dy = py-sy[sub][j], dz = pz-sz[sub][j];
            float vv = fmaf(dx, dx, fmaf(dy, dy, dz*dz));
            #pragma unroll
            for (int k = 0; k < KNN_; k++) {
                float lo = fminf(best[k], vv);
                vv = fmaxf(best[k], vv);
                best[k] = lo;
            }
        }
        float s = 0.f;
        #pragma unroll
        for (int k = 0; k < KNN_; k++) {
            float dn = fmaxf(best[k], REP_EPS);
            s += (RADIUS_ - sqrtf(dn)) * expf(-dn / BW2);
        }
        #pragma unroll
        for (int off = 16; off; off >>= 1) s += __shfl_down_sync(0xffffffffu, s, off);
        __shared__ float sw[8];
        if ((t & 31) == 0) sw[t >> 5] = s;
        __syncthreads();
        if (i == 0) {
            float tot = sw[sub*2] + sw[sub*2 + 1];
            atomicAdd(&g_accs[0], fmaxf(tot / (float)(FAC_*KNN_), 0.f));
        }
    }
}

// ---------------- kernel 2: float JV Hungarian + cls + final combine ----------------
__global__ void __launch_bounds__(256) k2(const float* __restrict__ logits,
                                          float* __restrict__ out)
{
    __shared__ float cost_s[B_][P_*Q_];
    __shared__ float u_s[B_][P_ + 1];
    __shared__ float red[3][256];
    int t = threadIdx.x;
    int w = t >> 5;        // warp = batch
    int lane = t & 31;
    const unsigned FULL = 0xffffffffu;

    // load all cost matrices
    const float* csrc = &g_costT[0][0][0];
    for (int idx = t; idx < B_*P_*Q_; idx += 256)
        (&cost_s[0][0])[idx] = csrc[idx];
    if (lane <= P_) u_s[w][lane] = 0.f;
    __syncthreads();

    // ---- JV on transposed 12x20 problem, fp32 duals, REDUX argmin ----
    float v = 0.f, minv = 0.f;
    int p = 0, way = 0, used = 0;

    for (int i = 1; i <= P_; i++) {
        if (lane == 0) p = i;
        minv = 1e30f; used = 0;
        int j0 = 0;
        while (true) {
            if (lane == j0) used = 1;
            int i0 = __shfl_sync(FULL, p, j0);
            float u0 = u_s[w][i0];
            bool active = (lane >= 1) && (lane <= Q_) && !used;
            if (active) {
                // JV invariant: reduced cost >= 0; clamp fp32 noise so bit-packing stays monotone
                float cur = fmaxf(cost_s[w][(i0-1)*Q_ + (lane-1)] - u0 - v, 0.f);
                if (cur < minv) { minv = cur; way = j0; }
            }
            unsigned key = active ? ((__float_as_uint(minv) & ~31u) | (unsigned)lane)
                                  : 0xFFFFFFFFu;
            key = __reduce_min_sync(FULL, key);
            int j1 = (int)(key & 31u);
            float delta = __shfl_sync(FULL, minv, j1);
            if (lane <= Q_) {
                if (used)           { u_s[w][p] += delta; v -= delta; }
                else if (lane >= 1) { minv -= delta; }
            }
            __syncwarp();
            j0 = j1;
            int pj = __shfl_sync(FULL, p, j0);
            if (pj == 0) break;
        }
        // augment along alternating path
        while (true) {
            int wy = __shfl_sync(FULL, way, j0);
            int pw = __shfl_sync(FULL, p, wy);
            if (lane == j0) p = pw;
            j0 = wy;
            if (j0 == 0) break;
        }
    }
    if (lane >= 1 && lane <= Q_ && p >= 1)
        g_rows[w][p - 1] = lane - 1;   // gt plane (p-1) matched to query (lane-1)
    __syncthreads();

    // ---- cls / param / pvd ----
    float c_cls = 0.f, c_par = 0.f, c_pvd = 0.f;
    if (t < B_*Q_) {
        int b = t / Q_, q = t % Q_;
        float tgt = 0.f;
        #pragma unroll
        for (int pp = 0; pp < P_; pp++) tgt += (g_rows[b][pp] == q) ? 1.f : 0.f;
        float x = logits[t];
        c_cls = fmaxf(x, 0.f) - x*tgt + log1pf(expf(-fabsf(x)));
    }
    if (t < B_*P_) {
        int b = t / P_, pp = t % P_;
        int r = g_rows[b][pp];
        c_par = g_nsim[b][r][pp] + g_ddiff[b][r][pp];
        c_pvd = (g_cnt[b][pp] > 0.f) ? g_cham[b][r][pp] : 0.f;
    }
    red[0][t] = c_cls; red[1][t] = c_par; red[2][t] = c_pvd;
    __syncthreads();
    for (int off = 128; off; off >>= 1) {
        if (t < off) {
            red[0][t] += red[0][t+off]; red[1][t] += red[1][t+off]; red[2][t] += red[2][t+off];
        }
        __syncthreads();
    }
    if (t == 0) {
        float ch1 = 0.5f * (g_accs[1] / (float)BM + g_accs[3] / (float)BG);
        float ch2 = 0.5f * (g_accs[2] / (float)BM + g_accs[4] / (float)BG);
        out[0] = red[0][0] / (float)(B_*Q_)
               + 0.5f  * red[1][0] / (float)(B_*P_)
               + 20.f  * red[2][0] / (float)(B_*P_)
               + g_accs[0] / (float)(B_*Q_)
               + ch1 + ch2;
    }
    // restore accumulators for next graph replay
    if (t < 8) g_accs[t] = 0.f;
}

// ---------------- host launcher ----------------
extern "C" void kernel_launch(void* const* d_in, const int* in_sizes, int n_in,
                              void* d_out, int out_size) {
    const float* pred_logits = nullptr;
    const float* pred_normals = nullptr;
    const float* pred_distances = nullptr;
    const float* gt_normals = nullptr;
    const float* gt_distances = nullptr;
    const void*  gt_masks = nullptr;
    const float* points = nullptr;
    const float* rec = nullptr;
    const float* gt = nullptr;
    int seen160 = 0;
    for (int i = 0; i < n_in; i++) {
        switch (in_sizes[i]) {
            case B_ * Q_:
                if (seen160++ == 0) pred_logits = (const float*)d_in[i];
                else pred_distances = (const float*)d_in[i];
                break;
            case B_ * Q_ * 3: pred_normals = (const float*)d_in[i]; break;
            case B_ * P_ * 3: gt_normals = (const float*)d_in[i]; break;
            case B_ * P_: gt_distances = (const float*)d_in[i]; break;
            case B_ * P_ * N_: gt_masks = d_in[i]; break;
            case B_ * N_ * 3: points = (const float*)d_in[i]; break;
            case B_ * M_ * 3: rec = (const float*)d_in[i]; break;
            case B_ * G_ * 3: gt = (const float*)d_in[i]; break;
            default: break;  // gt_index unused
        }
    }

    k1<<<K1_BLOCKS, 256>>>(points, pred_normals, pred_distances,
                           gt_normals, gt_distances, gt_masks, rec, gt);
    k2<<<1, 256>>>(pred_logits, (float*)d_out);
}